// round 1
// baseline (speedup 1.0000x reference)
#include <cuda_runtime.h>
#include <cuda_bf16.h>
#include <cstdint>

// Problem: x[N=32768, D=2048] fp32 row-major.
// u[d] = sum_n x[n][d]^2 + eps ; out = x * rsqrt(u) (broadcast over rows)

#define NROWS 32768
#define NCOLS 2048
#define NCOLS4 (NCOLS / 4)          // 512 float4 column-groups
#define ROWS_PER_CHUNK 128
#define ROW_CHUNKS (NROWS / ROWS_PER_CHUNK)   // 256
#define EPS 1e-6f

// Scratch: deterministic per-chunk partial sums (no atomics -> bitwise deterministic)
__device__ float g_part[ROW_CHUNKS * NCOLS];   // 2 MB
__device__ float g_scale[NCOLS];               // 8 KB

// ---------------------------------------------------------------------------
// Kernel 1: per-row-chunk column sum of squares.
// grid = (2, 256): blockIdx.x = column-block (256 float4 groups each),
//                  blockIdx.y = row chunk (128 rows).
// Each thread owns one float4 column-group; warp reads 512B contiguous / row.
// ---------------------------------------------------------------------------
__global__ void __launch_bounds__(256) colsq_kernel(const float4* __restrict__ x) {
    const int cg    = blockIdx.x * 256 + threadIdx.x;     // 0..511
    const int chunk = blockIdx.y;                          // 0..255

    const float4* p = x + (size_t)chunk * ROWS_PER_CHUNK * NCOLS4 + cg;

    float ax = 0.f, ay = 0.f, az = 0.f, aw = 0.f;
#pragma unroll 8
    for (int r = 0; r < ROWS_PER_CHUNK; ++r) {
        float4 v = __ldg(p + (size_t)r * NCOLS4);
        ax = fmaf(v.x, v.x, ax);
        ay = fmaf(v.y, v.y, ay);
        az = fmaf(v.z, v.z, az);
        aw = fmaf(v.w, v.w, aw);
    }

    float4* out = reinterpret_cast<float4*>(g_part) + (size_t)chunk * NCOLS4 + cg;
    *out = make_float4(ax, ay, az, aw);
}

// ---------------------------------------------------------------------------
// Kernel 2: fold the 256 chunk partials per column, compute rsqrt scale.
// 8 blocks x 256 threads = 2048 threads, one per column. Reads 2 MB (L2).
// ---------------------------------------------------------------------------
__global__ void __launch_bounds__(256) reduce_kernel() {
    const int c = blockIdx.x * 256 + threadIdx.x;   // 0..2047
    float s = 0.f;
#pragma unroll 8
    for (int k = 0; k < ROW_CHUNKS; ++k)
        s += g_part[(size_t)k * NCOLS + c];
    g_scale[c] = rsqrtf(s + EPS);
}

// ---------------------------------------------------------------------------
// Kernel 3: out = x * scale[col]. One float4 per thread.
// 16M float4 -> 65536 blocks x 256 threads. scale table (8KB) L1-resident.
// ---------------------------------------------------------------------------
__global__ void __launch_bounds__(256) scale_kernel(const float4* __restrict__ x,
                                                    float4* __restrict__ out) {
    const size_t i  = (size_t)blockIdx.x * 256 + threadIdx.x;
    const int   cg  = (int)(i & (NCOLS4 - 1));      // column group, NCOLS4 = 512 (pow2)

    float4 s = __ldg(reinterpret_cast<const float4*>(g_scale) + cg);
    float4 v = __ldg(x + i);
    v.x *= s.x; v.y *= s.y; v.z *= s.z; v.w *= s.w;
    out[i] = v;
}

// ---------------------------------------------------------------------------
extern "C" void kernel_launch(void* const* d_in, const int* in_sizes, int n_in,
                              void* d_out, int out_size) {
    const float4* x   = reinterpret_cast<const float4*>(d_in[0]);
    float4*       out = reinterpret_cast<float4*>(d_out);

    colsq_kernel<<<dim3(2, ROW_CHUNKS), 256>>>(x);
    reduce_kernel<<<NCOLS / 256, 256>>>();
    scale_kernel<<<(NROWS * NCOLS4) / 256, 256>>>(x, out);
}

// round 2
// speedup vs baseline: 1.0977x; 1.0977x over previous
#include <cuda_runtime.h>
#include <cuda_bf16.h>
#include <cstdint>

// x[N=32768, D=2048] fp32 row-major.
// u[d] = sum_n x[n][d]^2 + eps ; out = x * rsqrt(u)

#define NROWS 32768
#define NCOLS 2048
#define NCOLS4 (NCOLS / 4)                    // 512 float4 column-groups
#define ROWS_PER_CHUNK 32
#define ROW_CHUNKS (NROWS / ROWS_PER_CHUNK)   // 1024
#define SPLITS 32                             // stage-A fold width
#define CHUNKS_PER_SPLIT (ROW_CHUNKS / SPLITS) // 32
#define EPS 1e-6f

// Deterministic scratch (no atomics)
__device__ float g_part [ROW_CHUNKS * NCOLS];   // 8 MB
__device__ float g_part2[SPLITS * NCOLS];       // 256 KB
__device__ float g_scale[NCOLS];                // 8 KB

// ---------------------------------------------------------------------------
// K1: per-row-chunk column sum of squares.
// grid = (2, 1024): bx = column half (256 fl4 groups), by = 32-row chunk.
// ---------------------------------------------------------------------------
__global__ void __launch_bounds__(256) colsq_kernel(const float4* __restrict__ x) {
    const int cg    = blockIdx.x * 256 + threadIdx.x;   // 0..511
    const int chunk = blockIdx.y;                        // 0..1023

    const float4* p = x + (size_t)chunk * ROWS_PER_CHUNK * NCOLS4 + cg;

    float ax = 0.f, ay = 0.f, az = 0.f, aw = 0.f;
#pragma unroll 8
    for (int r = 0; r < ROWS_PER_CHUNK; ++r) {
        float4 v = __ldg(p + (size_t)r * NCOLS4);
        ax = fmaf(v.x, v.x, ax);
        ay = fmaf(v.y, v.y, ay);
        az = fmaf(v.z, v.z, az);
        aw = fmaf(v.w, v.w, aw);
    }

    reinterpret_cast<float4*>(g_part)[(size_t)chunk * NCOLS4 + cg] =
        make_float4(ax, ay, az, aw);
}

// ---------------------------------------------------------------------------
// K2a: fold 1024 chunk-partials -> 32 split-partials per column.
// grid = (8, 32): bx = column block (256 cols), by = split. Coalesced.
// ---------------------------------------------------------------------------
__global__ void __launch_bounds__(256) reduceA_kernel() {
    const int c     = blockIdx.x * 256 + threadIdx.x;  // 0..2047
    const int split = blockIdx.y;                      // 0..31
    float s = 0.f;
#pragma unroll
    for (int k = 0; k < CHUNKS_PER_SPLIT; ++k)
        s += g_part[(size_t)(split * CHUNKS_PER_SPLIT + k) * NCOLS + c];
    g_part2[(size_t)split * NCOLS + c] = s;
}

// ---------------------------------------------------------------------------
// K2b: fold 32 split-partials, rsqrt -> scale. 2048 threads.
// ---------------------------------------------------------------------------
__global__ void __launch_bounds__(256) reduceB_kernel() {
    const int c = blockIdx.x * 256 + threadIdx.x;
    float s = 0.f;
#pragma unroll
    for (int k = 0; k < SPLITS; ++k)
        s += g_part2[(size_t)k * NCOLS + c];
    g_scale[c] = rsqrtf(s + EPS);
}

// ---------------------------------------------------------------------------
// K3: out = x * scale[col].
// Each block handles 1024 consecutive float4 (256 thr x 4 iters).
// Blocks traverse x in REVERSE so the first waves hit the tail of x that
// K1's last waves left resident in L2. Streaming stores keep the output
// from evicting that read-side tail.
// ---------------------------------------------------------------------------
#define FL4_TOTAL (NROWS * NCOLS4)          // 16M float4
#define FL4_PER_BLOCK 1024
#define K3_BLOCKS (FL4_TOTAL / FL4_PER_BLOCK) // 16384

__global__ void __launch_bounds__(256) scale_kernel(const float4* __restrict__ x,
                                                    float4* __restrict__ out) {
    const int blk  = K3_BLOCKS - 1 - blockIdx.x;            // reversed
    const size_t base = (size_t)blk * FL4_PER_BLOCK + threadIdx.x;

#pragma unroll
    for (int it = 0; it < 4; ++it) {
        const size_t i  = base + (size_t)it * 256;
        const int    cg = (int)(i & (NCOLS4 - 1));           // NCOLS4=512 pow2

        float4 s = __ldg(reinterpret_cast<const float4*>(g_scale) + cg);
        float4 v = x[i];
        v.x *= s.x; v.y *= s.y; v.z *= s.z; v.w *= s.w;
        __stcs(out + i, v);
    }
}

// ---------------------------------------------------------------------------
extern "C" void kernel_launch(void* const* d_in, const int* in_sizes, int n_in,
                              void* d_out, int out_size) {
    const float4* x   = reinterpret_cast<const float4*>(d_in[0]);
    float4*       out = reinterpret_cast<float4*>(d_out);

    colsq_kernel  <<<dim3(2, ROW_CHUNKS), 256>>>(x);
    reduceA_kernel<<<dim3(NCOLS / 256, SPLITS), 256>>>();
    reduceB_kernel<<<NCOLS / 256, 256>>>();
    scale_kernel  <<<K3_BLOCKS, 256>>>(x, out);
}